// round 11
// baseline (speedup 1.0000x reference)
#include <cuda_runtime.h>
#include <cstdint>

// HairBundle SDE drift + constant diffusion. Streaming, memory-bound.
// Floor: 480MB traffic (160R + 320W). Kernel history: R5 70.8us (LDG+STS),
// R7 71.7us (cp.async, 87% occ), R8 69.3us (2-tile double buffer, 76.6% DRAM).
// R9: persistent warps, grid-stride tiles, steady-state 2-deep cp.async ring:
// reads outstanding ~continuously; next tile issued the moment a slot frees.

#define TPB 256
#define WPB (TPB / 32)
#define F4T 160                      // float4 per warp-tile = 128 rows
#define BLOCKS_RESIDENT 740          // 148 SMs x 5 blocks (launch_bounds 256,5)

__device__ __forceinline__ void hb_row(float x_hb, float x_a, float p_m,
                                       float p_gs, float p_t, float force,
                                       float* __restrict__ o) {
    float z    = 4.0f * (x_hb - x_a);                 // (x_hb - x_a)/DELTA
    float p_o  = 1.0f / (1.0f + __expf(-z));          // sigmoid
    float f_gs = 0.75f * (x_hb - x_a - 0.5f * p_o);
    o[0] = -f_gs - 0.6f * x_hb + force;
    o[1] = 0.1f * (f_gs - 0.45f * x_a - 0.35f * (1.0f - 0.9f * p_m));
    o[2] = 1.2f * p_o * (1.0f - p_m)  - 0.8f * p_m;
    o[3] = 0.7f * p_o * (1.0f - p_gs) - 0.5f * p_gs;
    o[4] = 0.3f * p_o * (1.0f - p_t)  - 0.4f * p_t;
}

__device__ __forceinline__ void cp_async16(uint32_t smem_addr, const void* gptr) {
    asm volatile("cp.async.cg.shared.global [%0], [%1], 16;\n"
                 :: "r"(smem_addr), "l"(gptr));
}

// issue one tile's reads (5 x cp.async.cg per lane) + commit as one group
__device__ __forceinline__ void issue_tile(uint32_t sslot,
                                           const float4* __restrict__ gsrc,
                                           int lane) {
    #pragma unroll
    for (int k = 0; k < 5; k++)
        cp_async16(sslot + (uint32_t)(lane + k * 32) * 16u, gsrc + lane + k * 32);
    asm volatile("cp.async.commit_group;\n" ::: "memory");
}

__device__ __forceinline__ void diffu_stg(float4* __restrict__ dst, int lane) {
    // period-5 f4 pattern; tile base % 5 == 0; 32 % 5 == 2
    int m = lane % 5;
    #pragma unroll
    for (int k = 0; k < 5; k++) {
        int p = m + 2 * k; p %= 5;
        float4 v = (p == 0) ? make_float4(0.05f, 0.02f, 0.0f,  0.0f)  :
                   (p == 1) ? make_float4(0.0f,  0.05f, 0.02f, 0.0f)  :
                   (p == 2) ? make_float4(0.0f,  0.0f,  0.05f, 0.02f) :
                   (p == 3) ? make_float4(0.0f,  0.0f,  0.0f,  0.05f) :
                              make_float4(0.02f, 0.0f,  0.0f,  0.0f);
        __stcs(dst + lane + k * 32, v);
    }
}

// compute 4 rows in place in a warp-private 160-f4 slab (lane slice i5=lane*5)
__device__ __forceinline__ void compute_tile(float4* __restrict__ sb, int lane,
                                             float force) {
    const int i5 = lane * 5;
    float4 a = sb[i5 + 0];
    float4 b = sb[i5 + 1];
    float o0[5], o1[5];
    hb_row(a.x, a.y, a.z, a.w, b.x, force, o0);       // row 0
    float4 c = sb[i5 + 2];
    hb_row(b.y, b.z, b.w, c.x, c.y, force, o1);       // row 1
    sb[i5 + 0] = make_float4(o0[0], o0[1], o0[2], o0[3]);
    sb[i5 + 1] = make_float4(o0[4], o1[0], o1[1], o1[2]);
    float4 d = sb[i5 + 3];
    float o2[5];
    hb_row(c.z, c.w, d.x, d.y, d.z, force, o2);       // row 2
    sb[i5 + 2] = make_float4(o1[3], o1[4], o2[0], o2[1]);
    float4 e = sb[i5 + 4];
    float o3[5];
    hb_row(d.w, e.x, e.y, e.z, e.w, force, o3);       // row 3
    sb[i5 + 3] = make_float4(o2[2], o2[3], o2[4], o3[0]);
    sb[i5 + 4] = make_float4(o3[1], o3[2], o3[3], o3[4]);
}

__device__ __forceinline__ void drift_stg(float4* __restrict__ dst,
                                          const float4* __restrict__ sb,
                                          int lane) {
    __stcs(dst + lane +   0, sb[lane +   0]);
    __stcs(dst + lane +  32, sb[lane +  32]);
    __stcs(dst + lane +  64, sb[lane +  64]);
    __stcs(dst + lane +  96, sb[lane +  96]);
    __stcs(dst + lane + 128, sb[lane + 128]);
}

__global__ __launch_bounds__(TPB, 5)
void hb_kernel(const float* __restrict__ t,
               const float4* __restrict__ x4,
               float4* __restrict__ drift4,
               float4* __restrict__ diffu4,
               int ntiles, int B) {
    __shared__ float4 buf[WPB][2][F4T];   // 40KB/block
    const int lane = threadIdx.x & 31;
    const int w    = threadIdx.x >> 5;
    const int wid  = blockIdx.x * WPB + w;            // global warp id
    const int tw   = gridDim.x * WPB;                  // total warps

    const float force = 0.5f * __sinf(6.283185307179586f * t[0]);

    uint32_t s0 = (uint32_t)__cvta_generic_to_shared(&buf[w][0][0]);
    uint32_t s1 = (uint32_t)__cvta_generic_to_shared(&buf[w][1][0]);

    // ---- prologue: fill the 2-deep ring ----
    int outstanding = 0;
    if (wid < ntiles) {
        issue_tile(s0, x4 + (size_t)wid * F4T, lane);
        diffu_stg(diffu4 + (size_t)wid * F4T, lane);
        outstanding++;
        if (wid + tw < ntiles) {
            issue_tile(s1, x4 + (size_t)(wid + tw) * F4T, lane);
            diffu_stg(diffu4 + (size_t)(wid + tw) * F4T, lane);
            outstanding++;
        }
    }

    // ---- steady state ----
    int slot = 0;
    for (int jc = wid; jc < ntiles; jc += tw, slot ^= 1) {
        if (outstanding == 2) {
            asm volatile("cp.async.wait_group 1;\n" ::: "memory");
        } else {
            asm volatile("cp.async.wait_group 0;\n" ::: "memory");
        }
        __syncwarp();

        float4* sb = &buf[w][slot][0];
        compute_tile(sb, lane, force);
        __syncwarp();
        drift_stg(drift4 + (size_t)jc * F4T, sb, lane);
        outstanding--;
        // all smem reads of this slot are complete here (each LDS feeding a
        // STG is scoreboard-serialized before the STGs, which precede these
        // cp.asyncs in program order) -> safe to re-issue into the slot.
        int jn = jc + 2 * tw;
        if (jn < ntiles) {
            issue_tile(slot ? s1 : s0, x4 + (size_t)jn * F4T, lane);
            diffu_stg(diffu4 + (size_t)jn * F4T, lane);
            outstanding++;
        }
        __syncwarp();
    }

    // ---- scalar remainder rows [ntiles*128, B): warp 0 only (empty for B=8M)
    if (wid == 0) {
        const float* xs = (const float*)x4;
        float* drs = (float*)drift4;
        float* dfs = (float*)diffu4;
        for (int r = ntiles * 128 + lane; r < B; r += 32) {
            const float* xr = xs + (size_t)r * 5;
            float o[5];
            hb_row(xr[0], xr[1], xr[2], xr[3], xr[4], force, o);
            float* dr = drs + (size_t)r * 5;
            float* gr = dfs + (size_t)r * 5;
            dr[0] = o[0]; dr[1] = o[1]; dr[2] = o[2]; dr[3] = o[3]; dr[4] = o[4];
            gr[0] = 0.05f; gr[1] = 0.02f; gr[2] = 0.0f; gr[3] = 0.0f; gr[4] = 0.0f;
        }
    }
}

extern "C" void kernel_launch(void* const* d_in, const int* in_sizes, int n_in,
                              void* d_out, int out_size) {
    const float* t  = (const float*)d_in[0];   // [1]
    const float* x  = (const float*)d_in[1];   // [B*5]
    float* out      = (float*)d_out;
    int B           = in_sizes[1] / 5;
    int nf4         = in_sizes[1] / 4;         // B*5 % 4 == 0 for B=8M
    float* drift    = out;
    float* diffu    = out + (size_t)out_size / 2;

    int ntiles  = nf4 / F4T;                   // 62500 for B=8M (exact)
    int nblocks = BLOCKS_RESIDENT;             // one resident wave
    int maxb    = (ntiles + WPB - 1) / WPB;    // don't over-launch tiny cases
    if (maxb < 1) maxb = 1;
    if (nblocks > maxb) nblocks = maxb;

    hb_kernel<<<nblocks, TPB>>>(t, (const float4*)x,
                                (float4*)drift, (float4*)diffu, ntiles, B);
}

// round 12
// speedup vs baseline: 1.1620x; 1.1620x over previous
#include <cuda_runtime.h>
#include <cstdint>

// HairBundle SDE drift + constant diffusion. Streaming, memory-bound.
// Floor: 480MB (160R+320W) -> ~60us @ 8TB/s. Totals: R5 74.2 (best), R7 76.7,
// R8 75.6, R9 86.1 (persistent loop FAILED). All structures pin ~6.0TB/s.
// R10: store side moved to cp.async.bulk S2G: drift = one 2560B bulk copy from
// the warp's smem slab; diffusion = one bulk copy from a block-constant slab.
// Kills 10 STG.128 + 10 LDS per warp-tile; writes become 2560B bursts.

#define TPB 256
#define WPB (TPB / 32)
#define F4T 160                      // float4 per warp-tile = 128 rows
#define TILE_BYTES (F4T * 16)        // 2560

__device__ __forceinline__ void hb_row(float x_hb, float x_a, float p_m,
                                       float p_gs, float p_t, float force,
                                       float* __restrict__ o) {
    float z    = 4.0f * (x_hb - x_a);                 // (x_hb - x_a)/DELTA
    float p_o  = 1.0f / (1.0f + __expf(-z));          // sigmoid
    float f_gs = 0.75f * (x_hb - x_a - 0.5f * p_o);
    o[0] = -f_gs - 0.6f * x_hb + force;
    o[1] = 0.1f * (f_gs - 0.45f * x_a - 0.35f * (1.0f - 0.9f * p_m));
    o[2] = 1.2f * p_o * (1.0f - p_m)  - 0.8f * p_m;
    o[3] = 0.7f * p_o * (1.0f - p_gs) - 0.5f * p_gs;
    o[4] = 0.3f * p_o * (1.0f - p_t)  - 0.4f * p_t;
}

__device__ __forceinline__ void cp_async16(uint32_t smem_addr, const void* gptr) {
    asm volatile("cp.async.cg.shared.global [%0], [%1], 16;\n"
                 :: "r"(smem_addr), "l"(gptr));
}

__device__ __forceinline__ void bulk_s2g(void* gptr, uint32_t smem_addr,
                                         uint32_t bytes) {
    asm volatile("cp.async.bulk.global.shared::cta.bulk_group [%0], [%1], %2;\n"
                 :: "l"(gptr), "r"(smem_addr), "r"(bytes) : "memory");
}

__global__ __launch_bounds__(TPB, 8)
void hb_kernel(const float* __restrict__ t,
               const float4* __restrict__ x4,
               float4* __restrict__ drift4,
               float4* __restrict__ diffu4,
               int nf4, int B) {
    __shared__ float4 buf[WPB][F4T];     // 20KB: in-place input->drift slabs
    __shared__ float4 slab[F4T];         // 2.5KB: constant diffusion tile
    const int tid  = threadIdx.x;
    const int lane = tid & 31;
    const int w    = tid >> 5;
    const int wid  = blockIdx.x * WPB + w;            // global warp id
    const int base = wid * F4T;                        // f4 offset (fits int)
    const bool full = (base + F4T <= nf4);

    // ---- issue this warp's reads first (overlaps slab fill + barrier) ----
    uint32_t sbase = (uint32_t)__cvta_generic_to_shared(&buf[w][0]);
    if (full) {
        #pragma unroll
        for (int k = 0; k < 5; k++)
            cp_async16(sbase + (uint32_t)(lane + k * 32) * 16u,
                       x4 + base + lane + k * 32);
        asm volatile("cp.async.commit_group;\n" ::: "memory");
    }

    // ---- diffusion slab: pattern period 5 f4; tile base % 5 == 0 always ----
    if (tid < F4T) {
        int p = tid % 5;
        slab[tid] = (p == 0) ? make_float4(0.05f, 0.02f, 0.0f,  0.0f)  :
                    (p == 1) ? make_float4(0.0f,  0.05f, 0.02f, 0.0f)  :
                    (p == 2) ? make_float4(0.0f,  0.0f,  0.05f, 0.02f) :
                    (p == 3) ? make_float4(0.0f,  0.0f,  0.0f,  0.05f) :
                               make_float4(0.02f, 0.0f,  0.0f,  0.0f);
    }
    __syncthreads();   // all threads reach this; slab visible block-wide

    const float force = 0.5f * __sinf(6.283185307179586f * t[0]);

    if (full) {
        asm volatile("cp.async.wait_group 0;\n" ::: "memory");
        __syncwarp();

        // compute 4 rows in place (lane slice i5 = lane*5)
        {
            const int i5 = lane * 5;
            float4 a = buf[w][i5 + 0];
            float4 b = buf[w][i5 + 1];
            float o0[5], o1[5];
            hb_row(a.x, a.y, a.z, a.w, b.x, force, o0);       // row 0
            float4 c = buf[w][i5 + 2];
            hb_row(b.y, b.z, b.w, c.x, c.y, force, o1);       // row 1
            buf[w][i5 + 0] = make_float4(o0[0], o0[1], o0[2], o0[3]);
            buf[w][i5 + 1] = make_float4(o0[4], o1[0], o1[1], o1[2]);
            float4 d = buf[w][i5 + 3];
            float o2[5];
            hb_row(c.z, c.w, d.x, d.y, d.z, force, o2);       // row 2
            buf[w][i5 + 2] = make_float4(o1[3], o1[4], o2[0], o2[1]);
            float4 e = buf[w][i5 + 4];
            float o3[5];
            hb_row(d.w, e.x, e.y, e.z, e.w, force, o3);       // row 3
            buf[w][i5 + 3] = make_float4(o2[2], o2[3], o2[4], o3[0]);
            buf[w][i5 + 4] = make_float4(o3[1], o3[2], o3[3], o3[4]);
        }
        __syncwarp();   // all lanes' smem writes done before bulk issue

        if (lane == 0) {
            asm volatile("fence.proxy.async.shared::cta;\n" ::: "memory");
            uint32_t sslab = (uint32_t)__cvta_generic_to_shared(&slab[0]);
            bulk_s2g(drift4 + base, sbase, TILE_BYTES);
            bulk_s2g(diffu4 + base, sslab, TILE_BYTES);
            asm volatile("cp.async.bulk.commit_group;\n" ::: "memory");
            asm volatile("cp.async.bulk.wait_group 0;\n" ::: "memory");
        }
    } else {
        // ---- partial warp: scalar per-row fallback (empty for B=8M) ----
        const float* xs = (const float*)x4;
        float* drs = (float*)drift4;
        float* dfs = (float*)diffu4;
        int row0 = wid * 128;                 // 160 f4 = 128 rows per warp
        for (int r = row0 + lane; r < B; r += 32) {
            const float* xr = xs + (size_t)r * 5;
            float o[5];
            hb_row(xr[0], xr[1], xr[2], xr[3], xr[4], force, o);
            float* dr = drs + (size_t)r * 5;
            float* gr = dfs + (size_t)r * 5;
            dr[0] = o[0]; dr[1] = o[1]; dr[2] = o[2]; dr[3] = o[3]; dr[4] = o[4];
            gr[0] = 0.05f; gr[1] = 0.02f; gr[2] = 0.0f; gr[3] = 0.0f; gr[4] = 0.0f;
        }
    }
}

extern "C" void kernel_launch(void* const* d_in, const int* in_sizes, int n_in,
                              void* d_out, int out_size) {
    const float* t  = (const float*)d_in[0];   // [1]
    const float* x  = (const float*)d_in[1];   // [B*5]
    float* out      = (float*)d_out;
    int B           = in_sizes[1] / 5;
    int nf4         = in_sizes[1] / 4;         // B*5 % 4 == 0 for B=8M
    float* drift    = out;
    float* diffu    = out + (size_t)out_size / 2;

    int nwarps  = (B + 127) / 128;             // 62500 for B=8M
    int nblocks = (nwarps + WPB - 1) / WPB;    // 7813

    hb_kernel<<<nblocks, TPB>>>(t, (const float4*)x,
                                (float4*)drift, (float4*)diffu, nf4, B);
}